// round 1
// baseline (speedup 1.0000x reference)
#include <cuda_runtime.h>
#include <math.h>

#define D_MODEL  1024
#define N_HEADS  16
#define HEAD_DIM 64
#define BATCH    4
#define SEQ      2048
#define M_TOTAL  (BATCH * SEQ)   // 8192

// ---------------------------------------------------------------------------
// Scratch (no allocation allowed -> __device__ globals)
// ---------------------------------------------------------------------------
__device__ float g_Q[(size_t)M_TOTAL * D_MODEL];   // [B,H,T,Dh]
__device__ float g_K[(size_t)M_TOTAL * D_MODEL];   // [B,H,T,Dh]
__device__ float g_V[(size_t)M_TOTAL * D_MODEL];   // [B,H,T,Dh]
__device__ float g_Y[(size_t)M_TOTAL * D_MODEL];   // [B,T,D]

// ---------------------------------------------------------------------------
// GEMM: C = A[M,K] @ B[N,K]^T + bias[N]
// BM=BN=128, BK=16, 256 threads, 8x8 register tile per thread.
// If HEADED: scatter into [B, H, T, Dh] layout instead of [M, N].
// ---------------------------------------------------------------------------
template <bool HEADED>
__global__ void __launch_bounds__(256, 2) gemm_bias_kernel(
    const float* __restrict__ A, const float* __restrict__ B,
    const float* __restrict__ bias, float* __restrict__ C,
    int M, int N, int K)
{
    constexpr int BM = 128, BN = 128, BK = 16;
    __shared__ float As[BK][BM + 4];
    __shared__ float Bs[BK][BN + 4];

    const int tid = threadIdx.x;
    const int tx = tid & 15;         // 0..15
    const int ty = tid >> 4;         // 0..15
    const int bm = blockIdx.y;
    const int bn = blockIdx.x;

    const float* Ablk = A + (size_t)bm * BM * K;
    const float* Bblk = B + (size_t)bn * BN * K;

    float acc[8][8];
#pragma unroll
    for (int i = 0; i < 8; i++)
#pragma unroll
        for (int j = 0; j < 8; j++) acc[i][j] = 0.0f;

    for (int kk = 0; kk < K; kk += BK) {
        // Load A tile (128x16) as 512 float4, 2 per thread, store transposed.
#pragma unroll
        for (int i = 0; i < 2; i++) {
            int idx = tid + i * 256;          // 0..511
            int row = idx >> 2;               // 0..127
            int c4  = (idx & 3) * 4;          // 0,4,8,12
            float4 v = *(const float4*)(Ablk + (size_t)row * K + kk + c4);
            As[c4 + 0][row] = v.x;
            As[c4 + 1][row] = v.y;
            As[c4 + 2][row] = v.z;
            As[c4 + 3][row] = v.w;
        }
        // Load B tile (128x16) likewise.
#pragma unroll
        for (int i = 0; i < 2; i++) {
            int idx = tid + i * 256;
            int row = idx >> 2;
            int c4  = (idx & 3) * 4;
            float4 v = *(const float4*)(Bblk + (size_t)row * K + kk + c4);
            Bs[c4 + 0][row] = v.x;
            Bs[c4 + 1][row] = v.y;
            Bs[c4 + 2][row] = v.z;
            Bs[c4 + 3][row] = v.w;
        }
        __syncthreads();

#pragma unroll
        for (int k = 0; k < BK; k++) {
            float a[8], b[8];
#pragma unroll
            for (int u = 0; u < 8; u++) a[u] = As[k][ty * 8 + u];
#pragma unroll
            for (int u = 0; u < 8; u++) b[u] = Bs[k][tx * 8 + u];
#pragma unroll
            for (int i = 0; i < 8; i++)
#pragma unroll
                for (int j = 0; j < 8; j++)
                    acc[i][j] = fmaf(a[i], b[j], acc[i][j]);
        }
        __syncthreads();
    }

    // Epilogue
#pragma unroll
    for (int i = 0; i < 8; i++) {
        int m = bm * BM + ty * 8 + i;
#pragma unroll
        for (int j = 0; j < 8; j++) {
            int n = bn * BN + tx * 8 + j;
            float val = acc[i][j] + bias[n];
            if (HEADED) {
                int b = m / SEQ, t = m % SEQ;
                int h = n >> 6, d = n & 63;
                C[(((size_t)(b * N_HEADS + h) * SEQ) + t) * HEAD_DIM + d] = val;
            } else {
                C[(size_t)m * N + n] = val;
            }
        }
    }
}

// ---------------------------------------------------------------------------
// Flash attention (causal). One CTA per (b*H+h, 64-query tile).
// Q/K/V in [B,H,T,Dh]. Output Y in [B,T,D].
// 256 threads; each thread owns a 4x4 micro-tile of the 64x64 score tile
// and a 4(rows) x 4(dh cols) micro-tile of the output accumulator.
// ---------------------------------------------------------------------------
#define ATTN_P 65   // smem pitch (floats) to dodge bank conflicts
#define ATTN_SMEM (4 * 64 * ATTN_P * sizeof(float))

__global__ void __launch_bounds__(256, 2) attn_kernel(
    const float* __restrict__ Q, const float* __restrict__ K,
    const float* __restrict__ V, float* __restrict__ Y)
{
    extern __shared__ float sm[];
    float* Qs = sm;                    // 64 x 65
    float* Ks = sm + 64 * ATTN_P;      // 64 x 65
    float* Vs = sm + 2 * 64 * ATTN_P;  // 64 x 65
    float* Ps = sm + 3 * 64 * ATTN_P;  // 64 x 65

    const int tid = threadIdx.x;
    const int tx = tid & 15;     // score-tile col group / dh col group
    const int ty = tid >> 4;     // score-tile row group
    const int qt = blockIdx.x;
    const int bh = blockIdx.y;   // b*H + h
    const int q0 = qt * 64;

    const float* Qp = Q + ((size_t)bh * SEQ + q0) * HEAD_DIM;

    // Load Q tile: 64x64 floats = 1024 float4, 4 per thread.
#pragma unroll
    for (int i = 0; i < 4; i++) {
        int idx = tid + i * 256;
        int row = idx >> 4;
        int c   = (idx & 15) * 4;
        float4 v = *(const float4*)(Qp + row * HEAD_DIM + c);
        Qs[row * ATTN_P + c + 0] = v.x;
        Qs[row * ATTN_P + c + 1] = v.y;
        Qs[row * ATTN_P + c + 2] = v.z;
        Qs[row * ATTN_P + c + 3] = v.w;
    }

    float m_i[4], l_i[4], o[4][4];
#pragma unroll
    for (int i = 0; i < 4; i++) {
        m_i[i] = -1e30f;
        l_i[i] = 0.0f;
#pragma unroll
        for (int k = 0; k < 4; k++) o[i][k] = 0.0f;
    }

    const float scale = 0.125f;  // 1/sqrt(64)

    for (int kt = 0; kt <= qt; kt++) {
        __syncthreads();  // previous PV must finish before reloading K/V
        const int k0 = kt * 64;
        const float* Kp = K + ((size_t)bh * SEQ + k0) * HEAD_DIM;
        const float* Vp = V + ((size_t)bh * SEQ + k0) * HEAD_DIM;
#pragma unroll
        for (int i = 0; i < 4; i++) {
            int idx = tid + i * 256;
            int row = idx >> 4;
            int c   = (idx & 15) * 4;
            float4 kv = *(const float4*)(Kp + row * HEAD_DIM + c);
            Ks[row * ATTN_P + c + 0] = kv.x;
            Ks[row * ATTN_P + c + 1] = kv.y;
            Ks[row * ATTN_P + c + 2] = kv.z;
            Ks[row * ATTN_P + c + 3] = kv.w;
            float4 vv = *(const float4*)(Vp + row * HEAD_DIM + c);
            Vs[row * ATTN_P + c + 0] = vv.x;
            Vs[row * ATTN_P + c + 1] = vv.y;
            Vs[row * ATTN_P + c + 2] = vv.z;
            Vs[row * ATTN_P + c + 3] = vv.w;
        }
        __syncthreads();

        // S = Q @ K^T (4x4 per thread)
        float s[4][4];
#pragma unroll
        for (int i = 0; i < 4; i++)
#pragma unroll
            for (int j = 0; j < 4; j++) s[i][j] = 0.0f;

#pragma unroll 16
        for (int d = 0; d < HEAD_DIM; d++) {
            float qf[4], kf[4];
#pragma unroll
            for (int i = 0; i < 4; i++) qf[i] = Qs[(ty * 4 + i) * ATTN_P + d];
#pragma unroll
            for (int j = 0; j < 4; j++) kf[j] = Ks[(tx * 4 + j) * ATTN_P + d];
#pragma unroll
            for (int i = 0; i < 4; i++)
#pragma unroll
                for (int j = 0; j < 4; j++)
                    s[i][j] = fmaf(qf[i], kf[j], s[i][j]);
        }

        const bool diag = (kt == qt);
#pragma unroll
        for (int i = 0; i < 4; i++) {
#pragma unroll
            for (int j = 0; j < 4; j++) {
                s[i][j] *= scale;
                if (diag && (tx * 4 + j > ty * 4 + i)) s[i][j] = -1e30f;
            }
        }

        // Online softmax per row (reduce across 16 lanes with same ty)
#pragma unroll
        for (int i = 0; i < 4; i++) {
            float rm = fmaxf(fmaxf(s[i][0], s[i][1]), fmaxf(s[i][2], s[i][3]));
#pragma unroll
            for (int off = 1; off < 16; off <<= 1)
                rm = fmaxf(rm, __shfl_xor_sync(0xffffffffu, rm, off));
            float newm = fmaxf(m_i[i], rm);
            float corr = __expf(m_i[i] - newm);
            m_i[i] = newm;
            float rs = 0.0f;
#pragma unroll
            for (int j = 0; j < 4; j++) {
                float p = __expf(s[i][j] - newm);
                s[i][j] = p;
                rs += p;
            }
#pragma unroll
            for (int off = 1; off < 16; off <<= 1)
                rs += __shfl_xor_sync(0xffffffffu, rs, off);
            l_i[i] = l_i[i] * corr + rs;
#pragma unroll
            for (int k = 0; k < 4; k++) o[i][k] *= corr;
#pragma unroll
            for (int j = 0; j < 4; j++)
                Ps[(ty * 4 + i) * ATTN_P + tx * 4 + j] = s[i][j];
        }
        __syncthreads();

        // O += P @ V   (rows = ty*4+i, dh cols = tx*4+k)
#pragma unroll 8
        for (int j = 0; j < 64; j++) {
            float pf[4], vf[4];
#pragma unroll
            for (int i = 0; i < 4; i++) pf[i] = Ps[(ty * 4 + i) * ATTN_P + j];
#pragma unroll
            for (int k = 0; k < 4; k++) vf[k] = Vs[j * ATTN_P + tx * 4 + k];
#pragma unroll
            for (int i = 0; i < 4; i++)
#pragma unroll
                for (int k = 0; k < 4; k++)
                    o[i][k] = fmaf(pf[i], vf[k], o[i][k]);
        }
    }

    // Epilogue: Y[b, t, h*64 + d]
    const int b = bh / N_HEADS;
    const int h = bh % N_HEADS;
#pragma unroll
    for (int i = 0; i < 4; i++) {
        float inv = 1.0f / l_i[i];
        int t = q0 + ty * 4 + i;
        float* yp = Y + ((size_t)b * SEQ + t) * D_MODEL + h * HEAD_DIM + tx * 4;
#pragma unroll
        for (int k = 0; k < 4; k++) yp[k] = o[i][k] * inv;
    }
}

// ---------------------------------------------------------------------------
// Launch
// ---------------------------------------------------------------------------
extern "C" void kernel_launch(void* const* d_in, const int* in_sizes, int n_in,
                              void* d_out, int out_size)
{
    const float* x  = (const float*)d_in[0];
    const float* Wq = (const float*)d_in[1];
    const float* bq = (const float*)d_in[2];
    const float* Wk = (const float*)d_in[3];
    const float* bk = (const float*)d_in[4];
    const float* Wv = (const float*)d_in[5];
    const float* bv = (const float*)d_in[6];
    const float* Wo = (const float*)d_in[7];
    const float* bo = (const float*)d_in[8];
    float* out = (float*)d_out;

    float *Qb, *Kb, *Vb, *Yb;
    cudaGetSymbolAddress((void**)&Qb, g_Q);
    cudaGetSymbolAddress((void**)&Kb, g_K);
    cudaGetSymbolAddress((void**)&Vb, g_V);
    cudaGetSymbolAddress((void**)&Yb, g_Y);

    static bool attr_set = false;
    if (!attr_set) {
        cudaFuncSetAttribute(attn_kernel,
                             cudaFuncAttributeMaxDynamicSharedMemorySize,
                             (int)ATTN_SMEM);
        attr_set = true;
    }

    dim3 ggrid(D_MODEL / 128, M_TOTAL / 128);  // (8, 64)
    gemm_bias_kernel<true><<<ggrid, 256>>>(x, Wq, bq, Qb, M_TOTAL, D_MODEL, D_MODEL);
    gemm_bias_kernel<true><<<ggrid, 256>>>(x, Wk, bk, Kb, M_TOTAL, D_MODEL, D_MODEL);
    gemm_bias_kernel<true><<<ggrid, 256>>>(x, Wv, bv, Vb, M_TOTAL, D_MODEL, D_MODEL);

    dim3 agrid(SEQ / 64, BATCH * N_HEADS);     // (32, 64)
    attn_kernel<<<agrid, 256, ATTN_SMEM>>>(Qb, Kb, Vb, Yb);

    gemm_bias_kernel<false><<<ggrid, 256>>>(Yb, Wo, bo, out, M_TOTAL, D_MODEL, D_MODEL);
}

// round 2
// speedup vs baseline: 3.1499x; 3.1499x over previous
#include <cuda_runtime.h>
#include <math.h>

#define D_MODEL  1024
#define N_HEADS  16
#define HEAD_DIM 64
#define BATCH    4
#define SEQ      2048
#define M_TOTAL  (BATCH * SEQ)   // 8192

// ---------------------------------------------------------------------------
// Scratch
// ---------------------------------------------------------------------------
__device__ float g_Q[(size_t)M_TOTAL * D_MODEL];   // [B,H,T,Dh]
__device__ float g_K[(size_t)M_TOTAL * D_MODEL];   // [B,H,T,Dh]
__device__ float g_V[(size_t)M_TOTAL * D_MODEL];   // [B,H,T,Dh]
__device__ float g_Y[(size_t)M_TOTAL * D_MODEL];   // [B,T,D]

// ---------------------------------------------------------------------------
// tf32 helpers
// ---------------------------------------------------------------------------
__device__ __forceinline__ unsigned f2tf(float f) {
    unsigned r;
    asm("cvt.rna.tf32.f32 %0, %1;" : "=r"(r) : "f"(f));
    return r;
}

__device__ __forceinline__ void mma_tf32(float c[4],
    unsigned a0, unsigned a1, unsigned a2, unsigned a3,
    unsigned b0, unsigned b1)
{
    asm volatile(
        "mma.sync.aligned.m16n8k8.row.col.f32.tf32.tf32.f32 "
        "{%0,%1,%2,%3}, {%4,%5,%6,%7}, {%8,%9}, {%0,%1,%2,%3};"
        : "+f"(c[0]), "+f"(c[1]), "+f"(c[2]), "+f"(c[3])
        : "r"(a0), "r"(a1), "r"(a2), "r"(a3), "r"(b0), "r"(b1));
}

// ---------------------------------------------------------------------------
// GEMM: C = A[M,K] @ B[N,K]^T + bias,  M=8192, N=1024, K=1024
// BM=256, BN=128, BK=32. 256 threads = 8 warps (4x2), warp tile 64x64.
// smem pitch 36 -> conflict-free tf32 fragment loads. Double buffered.
// ---------------------------------------------------------------------------
#define GK 1024
#define GN 1024
#define G_PA 36
#define G_ABUF (256 * G_PA)            // 9216 words
#define G_BBUF (128 * G_PA)            // 4608 words
#define G_BUF  (G_ABUF + G_BBUF)       // 13824 words
#define GEMM_SMEM (2 * G_BUF * 4)      // 110592 bytes

template <bool HEADED>
__global__ void __launch_bounds__(256, 1) gemm_tf32_kernel(
    const float* __restrict__ A, const float* __restrict__ B,
    const float* __restrict__ bias, float* __restrict__ C)
{
    extern __shared__ unsigned smg[];
    const int tid  = threadIdx.x;
    const int lane = tid & 31;
    const int w    = tid >> 5;
    const int wm   = w & 3;        // 0..3
    const int wn   = w >> 2;       // 0..1
    const int g    = lane >> 2;    // 0..7
    const int q    = lane & 3;     // 0..3
    const int bm   = blockIdx.y;
    const int bn   = blockIdx.x;

    const float* Ab = A + (size_t)bm * 256 * GK;
    const float* Bb = B + (size_t)bn * 128 * GK;

    float acc[4][8][4];
#pragma unroll
    for (int mt = 0; mt < 4; mt++)
#pragma unroll
        for (int nt = 0; nt < 8; nt++)
#pragma unroll
            for (int i = 0; i < 4; i++) acc[mt][nt][i] = 0.0f;

    float4 aSt[8], bSt[4];

#define G_LOAD(KK)                                                          \
    {                                                                       \
        _Pragma("unroll")                                                   \
        for (int i = 0; i < 8; i++) {                                       \
            int idx = i * 256 + tid;                                        \
            int r = idx >> 3, c = (idx & 7) << 2;                           \
            aSt[i] = *(const float4*)(Ab + (size_t)r * GK + (KK) + c);      \
        }                                                                   \
        _Pragma("unroll")                                                   \
        for (int i = 0; i < 4; i++) {                                       \
            int idx = i * 256 + tid;                                        \
            int r = idx >> 3, c = (idx & 7) << 2;                           \
            bSt[i] = *(const float4*)(Bb + (size_t)r * GK + (KK) + c);      \
        }                                                                   \
    }

#define G_STORE(BUF)                                                        \
    {                                                                       \
        unsigned* As_ = smg + (BUF) * G_BUF;                                \
        unsigned* Bs_ = As_ + G_ABUF;                                       \
        _Pragma("unroll")                                                   \
        for (int i = 0; i < 8; i++) {                                       \
            int idx = i * 256 + tid;                                        \
            int r = idx >> 3, c = (idx & 7) << 2;                           \
            uint4 u;                                                        \
            u.x = f2tf(aSt[i].x); u.y = f2tf(aSt[i].y);                     \
            u.z = f2tf(aSt[i].z); u.w = f2tf(aSt[i].w);                     \
            *(uint4*)&As_[r * G_PA + c] = u;                                \
        }                                                                   \
        _Pragma("unroll")                                                   \
        for (int i = 0; i < 4; i++) {                                       \
            int idx = i * 256 + tid;                                        \
            int r = idx >> 3, c = (idx & 7) << 2;                           \
            uint4 u;                                                        \
            u.x = f2tf(bSt[i].x); u.y = f2tf(bSt[i].y);                     \
            u.z = f2tf(bSt[i].z); u.w = f2tf(bSt[i].w);                     \
            *(uint4*)&Bs_[r * G_PA + c] = u;                                \
        }                                                                   \
    }

    G_LOAD(0);
    G_STORE(0);
    __syncthreads();

    for (int kk = 0; kk < GK; kk += 32) {
        const int buf = (kk >> 5) & 1;
        const bool more = (kk + 32) < GK;
        if (more) G_LOAD(kk + 32);

        const unsigned* As = smg + buf * G_BUF;
        const unsigned* Bs = As + G_ABUF;

#pragma unroll
        for (int ks = 0; ks < 4; ks++) {
            const int k = ks * 8;
            unsigned af[4][4], bf[8][2];
#pragma unroll
            for (int mt = 0; mt < 4; mt++) {
                int r = wm * 64 + mt * 16 + g;
                af[mt][0] = As[r * G_PA + k + q];
                af[mt][1] = As[(r + 8) * G_PA + k + q];
                af[mt][2] = As[r * G_PA + k + q + 4];
                af[mt][3] = As[(r + 8) * G_PA + k + q + 4];
            }
#pragma unroll
            for (int nt = 0; nt < 8; nt++) {
                int cc = wn * 64 + nt * 8 + g;
                bf[nt][0] = Bs[cc * G_PA + k + q];
                bf[nt][1] = Bs[cc * G_PA + k + q + 4];
            }
#pragma unroll
            for (int mt = 0; mt < 4; mt++)
#pragma unroll
                for (int nt = 0; nt < 8; nt++)
                    mma_tf32(acc[mt][nt], af[mt][0], af[mt][1], af[mt][2], af[mt][3],
                             bf[nt][0], bf[nt][1]);
        }

        if (more) G_STORE(buf ^ 1);
        __syncthreads();
    }

    // Epilogue
#pragma unroll
    for (int mt = 0; mt < 4; mt++) {
        int m0 = bm * 256 + wm * 64 + mt * 16 + g;
        int m1 = m0 + 8;
#pragma unroll
        for (int nt = 0; nt < 8; nt++) {
            int n0 = bn * 128 + wn * 64 + nt * 8 + 2 * q;
            int n1 = n0 + 1;
            float b0 = bias[n0], b1 = bias[n1];
            float v00 = acc[mt][nt][0] + b0;
            float v01 = acc[mt][nt][1] + b1;
            float v10 = acc[mt][nt][2] + b0;
            float v11 = acc[mt][nt][3] + b1;
            if (HEADED) {
                int bb0 = m0 / SEQ, t0 = m0 % SEQ;
                int bb1 = m1 / SEQ, t1 = m1 % SEQ;
                int h0 = n0 >> 6, d0 = n0 & 63;
                int h1 = n1 >> 6, d1 = n1 & 63;
                C[(((size_t)(bb0 * N_HEADS + h0) * SEQ) + t0) * HEAD_DIM + d0] = v00;
                C[(((size_t)(bb0 * N_HEADS + h1) * SEQ) + t0) * HEAD_DIM + d1] = v01;
                C[(((size_t)(bb1 * N_HEADS + h0) * SEQ) + t1) * HEAD_DIM + d0] = v10;
                C[(((size_t)(bb1 * N_HEADS + h1) * SEQ) + t1) * HEAD_DIM + d1] = v11;
            } else {
                C[(size_t)m0 * GN + n0] = v00;
                C[(size_t)m0 * GN + n1] = v01;
                C[(size_t)m1 * GN + n0] = v10;
                C[(size_t)m1 * GN + n1] = v11;
            }
        }
    }
#undef G_LOAD
#undef G_STORE
}

// ---------------------------------------------------------------------------
// Flash attention with tf32 mma. CTA = 64 q-rows for one (b,h).
// 8 warps (4x2). QK: warp tile 16 rows x 32 keys. PV computes O^T = V^T @ P^T
// (warp tile 16 d x 32 qrows) so V/P stay in natural layouts.
// Qs/Ks/Ps pitch 68, Vs pitch 72: all fragment LDS conflict-free.
// Ps overlays Ks. smem ~54.5 KB.
// ---------------------------------------------------------------------------
#define A_PQ 68
#define A_PV 72
#define A_QS 0
#define A_KS (64 * A_PQ)            // 4352
#define A_VS (2 * 64 * A_PQ)        // 8704
#define A_RED (A_VS + 64 * A_PV)    // 13312
#define ATTN_SMEM ((A_RED + 320) * 4)

__global__ void __launch_bounds__(256, 2) attn_tf32_kernel(
    const float* __restrict__ Q, const float* __restrict__ K,
    const float* __restrict__ V, float* __restrict__ Y)
{
    extern __shared__ unsigned sma[];
    unsigned* Qs = sma + A_QS;
    unsigned* Ks = sma + A_KS;
    unsigned* Ps = Ks;                       // overlay
    unsigned* Vs = sma + A_VS;
    float* pmx  = (float*)(sma + A_RED);         // [2][64]
    float* psm  = (float*)(sma + A_RED + 128);   // [2][64]
    float* scor = (float*)(sma + A_RED + 256);   // [64]

    const int tid  = threadIdx.x;
    const int lane = tid & 31;
    const int w    = tid >> 5;
    const int wm   = w & 3;
    const int wn   = w >> 2;
    const int g    = lane >> 2;
    const int q    = lane & 3;
    const int qt   = blockIdx.x;
    const int bh   = blockIdx.y;
    const int q0   = qt * 64;

    const int r0 = wm * 16 + g;   // local row (softmax ownership)
    const int r1 = r0 + 8;

    // Load Q (fp32 -> tf32) into Qs
    {
        const float* Qp = Q + ((size_t)bh * SEQ + q0) * HEAD_DIM;
#pragma unroll
        for (int i = 0; i < 4; i++) {
            int idx = i * 256 + tid;
            int row = idx >> 4, c4 = (idx & 15) << 2;
            float4 v = *(const float4*)(Qp + row * HEAD_DIM + c4);
            uint4 u;
            u.x = f2tf(v.x); u.y = f2tf(v.y); u.z = f2tf(v.z); u.w = f2tf(v.w);
            *(uint4*)&Qs[row * A_PQ + c4] = u;
        }
    }

    float o[4][4];
#pragma unroll
    for (int nt = 0; nt < 4; nt++)
#pragma unroll
        for (int i = 0; i < 4; i++) o[nt][i] = 0.0f;
    float m0 = -1e30f, m1 = -1e30f, l0 = 0.0f, l1 = 0.0f;

    for (int kt = 0; kt <= qt; kt++) {
        __syncthreads();   // guards Ks(=Ps)/Vs reuse + Q first time
        const int k0 = kt * 64;
        {
            const float* Kp = K + ((size_t)bh * SEQ + k0) * HEAD_DIM;
            const float* Vp = V + ((size_t)bh * SEQ + k0) * HEAD_DIM;
#pragma unroll
            for (int i = 0; i < 4; i++) {
                int idx = i * 256 + tid;
                int row = idx >> 4, c4 = (idx & 15) << 2;
                float4 kv = *(const float4*)(Kp + row * HEAD_DIM + c4);
                uint4 uk;
                uk.x = f2tf(kv.x); uk.y = f2tf(kv.y); uk.z = f2tf(kv.z); uk.w = f2tf(kv.w);
                *(uint4*)&Ks[row * A_PQ + c4] = uk;
                float4 vv = *(const float4*)(Vp + row * HEAD_DIM + c4);
                uint4 uv;
                uv.x = f2tf(vv.x); uv.y = f2tf(vv.y); uv.z = f2tf(vv.z); uv.w = f2tf(vv.w);
                *(uint4*)&Vs[row * A_PV + c4] = uv;
            }
        }
        __syncthreads();

        // ---- S = Q @ K^T (warp: rows wm*16.., cols wn*32..)
        float sc[4][4];
#pragma unroll
        for (int nt = 0; nt < 4; nt++)
#pragma unroll
            for (int i = 0; i < 4; i++) sc[nt][i] = 0.0f;

#pragma unroll
        for (int ks = 0; ks < 8; ks++) {
            const int k = ks * 8;
            unsigned a0 = Qs[r0 * A_PQ + k + q];
            unsigned a1 = Qs[r1 * A_PQ + k + q];
            unsigned a2 = Qs[r0 * A_PQ + k + q + 4];
            unsigned a3 = Qs[r1 * A_PQ + k + q + 4];
#pragma unroll
            for (int nt = 0; nt < 4; nt++) {
                int col = wn * 32 + nt * 8 + g;
                unsigned b0 = Ks[col * A_PQ + k + q];
                unsigned b1 = Ks[col * A_PQ + k + q + 4];
                mma_tf32(sc[nt], a0, a1, a2, a3, b0, b1);
            }
        }

        // ---- scale + causal mask
        const bool diag = (kt == qt);
#pragma unroll
        for (int nt = 0; nt < 4; nt++) {
            int cl = wn * 32 + nt * 8 + 2 * q;
            sc[nt][0] *= 0.125f; sc[nt][1] *= 0.125f;
            sc[nt][2] *= 0.125f; sc[nt][3] *= 0.125f;
            if (diag) {
                if (cl     > r0) sc[nt][0] = -1e30f;
                if (cl + 1 > r0) sc[nt][1] = -1e30f;
                if (cl     > r1) sc[nt][2] = -1e30f;
                if (cl + 1 > r1) sc[nt][3] = -1e30f;
            }
        }

        // ---- row max over this warp's 32 cols
        float rm0 = -1e30f, rm1 = -1e30f;
#pragma unroll
        for (int nt = 0; nt < 4; nt++) {
            rm0 = fmaxf(rm0, fmaxf(sc[nt][0], sc[nt][1]));
            rm1 = fmaxf(rm1, fmaxf(sc[nt][2], sc[nt][3]));
        }
        rm0 = fmaxf(rm0, __shfl_xor_sync(0xffffffffu, rm0, 1));
        rm0 = fmaxf(rm0, __shfl_xor_sync(0xffffffffu, rm0, 2));
        rm1 = fmaxf(rm1, __shfl_xor_sync(0xffffffffu, rm1, 1));
        rm1 = fmaxf(rm1, __shfl_xor_sync(0xffffffffu, rm1, 2));

        // ---- exp, partial sums
        float s0 = 0.0f, s1 = 0.0f;
#pragma unroll
        for (int nt = 0; nt < 4; nt++) {
            sc[nt][0] = __expf(sc[nt][0] - rm0);
            sc[nt][1] = __expf(sc[nt][1] - rm0);
            sc[nt][2] = __expf(sc[nt][2] - rm1);
            sc[nt][3] = __expf(sc[nt][3] - rm1);
            s0 += sc[nt][0] + sc[nt][1];
            s1 += sc[nt][2] + sc[nt][3];
        }
        s0 += __shfl_xor_sync(0xffffffffu, s0, 1);
        s0 += __shfl_xor_sync(0xffffffffu, s0, 2);
        s1 += __shfl_xor_sync(0xffffffffu, s1, 1);
        s1 += __shfl_xor_sync(0xffffffffu, s1, 2);

        if (q == 0) {
            pmx[wn * 64 + r0] = rm0;  psm[wn * 64 + r0] = s0;
            pmx[wn * 64 + r1] = rm1;  psm[wn * 64 + r1] = s1;
        }
        __syncthreads();

        // ---- combine across the two n-warps; online update (per-thread state)
        float ma0 = pmx[r0], mb0 = pmx[64 + r0];
        float mt0 = fmaxf(ma0, mb0);
        float st0 = psm[r0] * __expf(ma0 - mt0) + psm[64 + r0] * __expf(mb0 - mt0);
        float mn0 = fmaxf(m0, mt0);
        float cr0 = __expf(m0 - mn0);
        l0 = l0 * cr0 + st0 * __expf(mt0 - mn0);

        float ma1 = pmx[r1], mb1 = pmx[64 + r1];
        float mt1 = fmaxf(ma1, mb1);
        float st1 = psm[r1] * __expf(ma1 - mt1) + psm[64 + r1] * __expf(mb1 - mt1);
        float mn1 = fmaxf(m1, mt1);
        float cr1 = __expf(m1 - mn1);
        l1 = l1 * cr1 + st1 * __expf(mt1 - mn1);

        float pf0 = __expf(rm0 - mn0);
        float pf1 = __expf(rm1 - mn1);
        m0 = mn0; m1 = mn1;

        if (wn == 0 && q == 0) { scor[r0] = cr0; scor[r1] = cr1; }

        // ---- write P (tf32) into Ps (= Ks region; all Ks reads done)
#pragma unroll
        for (int nt = 0; nt < 4; nt++) {
            int cl = wn * 32 + nt * 8 + 2 * q;
            Ps[r0 * A_PQ + cl]     = f2tf(sc[nt][0] * pf0);
            Ps[r0 * A_PQ + cl + 1] = f2tf(sc[nt][1] * pf0);
            Ps[r1 * A_PQ + cl]     = f2tf(sc[nt][2] * pf1);
            Ps[r1 * A_PQ + cl + 1] = f2tf(sc[nt][3] * pf1);
        }
        __syncthreads();

        // ---- rescale O by corr (cols of O^T are q-rows)
#pragma unroll
        for (int nt = 0; nt < 4; nt++) {
            int cl = wn * 32 + nt * 8 + 2 * q;
            float ca = scor[cl], cb = scor[cl + 1];
            o[nt][0] *= ca; o[nt][1] *= cb;
            o[nt][2] *= ca; o[nt][3] *= cb;
        }

        // ---- O^T += V^T @ P^T
        const int d0 = wm * 16 + g;
        const int d1 = d0 + 8;
#pragma unroll
        for (int ks = 0; ks < 8; ks++) {
            const int k = ks * 8;
            unsigned a0 = Vs[(k + q) * A_PV + d0];
            unsigned a1 = Vs[(k + q) * A_PV + d1];
            unsigned a2 = Vs[(k + q + 4) * A_PV + d0];
            unsigned a3 = Vs[(k + q + 4) * A_PV + d1];
#pragma unroll
            for (int nt = 0; nt < 4; nt++) {
                int cq = wn * 32 + nt * 8 + g;
                unsigned b0 = Ps[cq * A_PQ + k + q];
                unsigned b1 = Ps[cq * A_PQ + k + q + 4];
                mma_tf32(o[nt], a0, a1, a2, a3, b0, b1);
            }
        }
    }

    // ---- epilogue: publish l, normalize, write Y^T back as [B,T,D]
    __syncthreads();
    if (wn == 0 && q == 0) { scor[r0] = l0; scor[r1] = l1; }
    __syncthreads();

    const int b = bh >> 4;
    const int h = bh & 15;
    float* Yb = Y + ((size_t)b * SEQ + q0) * D_MODEL + h * HEAD_DIM;
    const int d0 = wm * 16 + g;
    const int d1 = d0 + 8;
#pragma unroll
    for (int nt = 0; nt < 4; nt++) {
        int cl = wn * 32 + nt * 8 + 2 * q;
        float inv0 = 1.0f / scor[cl];
        float inv1 = 1.0f / scor[cl + 1];
        Yb[(size_t)cl * D_MODEL + d0]       = o[nt][0] * inv0;
        Yb[(size_t)(cl + 1) * D_MODEL + d0] = o[nt][1] * inv1;
        Yb[(size_t)cl * D_MODEL + d1]       = o[nt][2] * inv0;
        Yb[(size_t)(cl + 1) * D_MODEL + d1] = o[nt][3] * inv1;
    }
}

// ---------------------------------------------------------------------------
// Launch
// ---------------------------------------------------------------------------
extern "C" void kernel_launch(void* const* d_in, const int* in_sizes, int n_in,
                              void* d_out, int out_size)
{
    const float* x  = (const float*)d_in[0];
    const float* Wq = (const float*)d_in[1];
    const float* bq = (const float*)d_in[2];
    const float* Wk = (const float*)d_in[3];
    const float* bk = (const float*)d_in[4];
    const float* Wv = (const float*)d_in[5];
    const float* bv = (const float*)d_in[6];
    const float* Wo = (const float*)d_in[7];
    const float* bo = (const float*)d_in[8];
    float* out = (float*)d_out;

    float *Qb, *Kb, *Vb, *Yb;
    cudaGetSymbolAddress((void**)&Qb, g_Q);
    cudaGetSymbolAddress((void**)&Kb, g_K);
    cudaGetSymbolAddress((void**)&Vb, g_V);
    cudaGetSymbolAddress((void**)&Yb, g_Y);

    static bool attr_set = false;
    if (!attr_set) {
        cudaFuncSetAttribute(gemm_tf32_kernel<true>,
                             cudaFuncAttributeMaxDynamicSharedMemorySize, GEMM_SMEM);
        cudaFuncSetAttribute(gemm_tf32_kernel<false>,
                             cudaFuncAttributeMaxDynamicSharedMemorySize, GEMM_SMEM);
        cudaFuncSetAttribute(attn_tf32_kernel,
                             cudaFuncAttributeMaxDynamicSharedMemorySize, ATTN_SMEM);
        attr_set = true;
    }

    dim3 ggrid(GN / 128, M_TOTAL / 256);   // (8, 32)
    gemm_tf32_kernel<true><<<ggrid, 256, GEMM_SMEM>>>(x, Wq, bq, Qb);
    gemm_tf32_kernel<true><<<ggrid, 256, GEMM_SMEM>>>(x, Wk, bk, Kb);
    gemm_tf32_kernel<true><<<ggrid, 256, GEMM_SMEM>>>(x, Wv, bv, Vb);

    dim3 agrid(SEQ / 64, BATCH * N_HEADS); // (32, 64)
    attn_tf32_kernel<<<agrid, 256, ATTN_SMEM>>>(Qb, Kb, Vb, Yb);

    gemm_tf32_kernel<false><<<ggrid, 256, GEMM_SMEM>>>(Yb, Wo, bo, out);
}

// round 3
// speedup vs baseline: 3.5115x; 1.1148x over previous
#include <cuda_runtime.h>
#include <math.h>

#define D_MODEL  1024
#define N_HEADS  16
#define HEAD_DIM 64
#define BATCH    4
#define SEQ      2048
#define M_TOTAL  (BATCH * SEQ)   // 8192

// ---------------------------------------------------------------------------
// Scratch
// ---------------------------------------------------------------------------
__device__ float g_Q[(size_t)M_TOTAL * D_MODEL];   // [B,H,T,Dh]
__device__ float g_K[(size_t)M_TOTAL * D_MODEL];   // [B,H,T,Dh]
__device__ float g_V[(size_t)M_TOTAL * D_MODEL];   // [B,H,T,Dh]
__device__ float g_Y[(size_t)M_TOTAL * D_MODEL];   // [B,T,D]

// ---------------------------------------------------------------------------
// tf32 helpers
// ---------------------------------------------------------------------------
__device__ __forceinline__ unsigned f2tf(float f) {
    unsigned r;
    asm("cvt.rna.tf32.f32 %0, %1;" : "=r"(r) : "f"(f));
    return r;
}

__device__ __forceinline__ void mma_tf32(float c[4],
    unsigned a0, unsigned a1, unsigned a2, unsigned a3,
    unsigned b0, unsigned b1)
{
    asm volatile(
        "mma.sync.aligned.m16n8k8.row.col.f32.tf32.tf32.f32 "
        "{%0,%1,%2,%3}, {%4,%5,%6,%7}, {%8,%9}, {%0,%1,%2,%3};"
        : "+f"(c[0]), "+f"(c[1]), "+f"(c[2]), "+f"(c[3])
        : "r"(a0), "r"(a1), "r"(a2), "r"(a3), "r"(b0), "r"(b1));
}

// ---------------------------------------------------------------------------
// GEMM: C = A[M,K] @ B[N,K]^T + bias,  M=8192, N=1024, K=1024
// BM=256, BN=128, BK=32. 256 threads = 8 warps (4x2), warp tile 64x64.
// blockIdx.z selects among up to 3 (B, bias, C) sets (fused QKV).
// ---------------------------------------------------------------------------
#define GK 1024
#define GN 1024
#define G_PA 36
#define G_ABUF (256 * G_PA)
#define G_BBUF (128 * G_PA)
#define G_BUF  (G_ABUF + G_BBUF)
#define GEMM_SMEM (2 * G_BUF * 4)

template <bool HEADED>
__global__ void __launch_bounds__(256, 1) gemm_tf32_kernel(
    const float* __restrict__ A,
    const float* __restrict__ B0, const float* __restrict__ bias0, float* __restrict__ C0,
    const float* __restrict__ B1, const float* __restrict__ bias1, float* __restrict__ C1,
    const float* __restrict__ B2, const float* __restrict__ bias2, float* __restrict__ C2)
{
    extern __shared__ unsigned smg[];
    const int z = blockIdx.z;
    const float* B    = (z == 0) ? B0    : (z == 1) ? B1    : B2;
    const float* bias = (z == 0) ? bias0 : (z == 1) ? bias1 : bias2;
    float*       C    = (z == 0) ? C0    : (z == 1) ? C1    : C2;

    const int tid  = threadIdx.x;
    const int lane = tid & 31;
    const int w    = tid >> 5;
    const int wm   = w & 3;
    const int wn   = w >> 2;
    const int g    = lane >> 2;
    const int q    = lane & 3;
    const int bm   = blockIdx.y;
    const int bn   = blockIdx.x;

    const float* Ab = A + (size_t)bm * 256 * GK;
    const float* Bb = B + (size_t)bn * 128 * GK;

    float acc[4][8][4];
#pragma unroll
    for (int mt = 0; mt < 4; mt++)
#pragma unroll
        for (int nt = 0; nt < 8; nt++)
#pragma unroll
            for (int i = 0; i < 4; i++) acc[mt][nt][i] = 0.0f;

    float4 aSt[8], bSt[4];

#define G_LOAD(KK)                                                          \
    {                                                                       \
        _Pragma("unroll")                                                   \
        for (int i = 0; i < 8; i++) {                                       \
            int idx = i * 256 + tid;                                        \
            int r = idx >> 3, c = (idx & 7) << 2;                           \
            aSt[i] = *(const float4*)(Ab + (size_t)r * GK + (KK) + c);      \
        }                                                                   \
        _Pragma("unroll")                                                   \
        for (int i = 0; i < 4; i++) {                                       \
            int idx = i * 256 + tid;                                        \
            int r = idx >> 3, c = (idx & 7) << 2;                           \
            bSt[i] = *(const float4*)(Bb + (size_t)r * GK + (KK) + c);      \
        }                                                                   \
    }

#define G_STORE(BUF)                                                        \
    {                                                                       \
        unsigned* As_ = smg + (BUF) * G_BUF;                                \
        unsigned* Bs_ = As_ + G_ABUF;                                       \
        _Pragma("unroll")                                                   \
        for (int i = 0; i < 8; i++) {                                       \
            int idx = i * 256 + tid;                                        \
            int r = idx >> 3, c = (idx & 7) << 2;                           \
            uint4 u;                                                        \
            u.x = f2tf(aSt[i].x); u.y = f2tf(aSt[i].y);                     \
            u.z = f2tf(aSt[i].z); u.w = f2tf(aSt[i].w);                     \
            *(uint4*)&As_[r * G_PA + c] = u;                                \
        }                                                                   \
        _Pragma("unroll")                                                   \
        for (int i = 0; i < 4; i++) {                                       \
            int idx = i * 256 + tid;                                        \
            int r = idx >> 3, c = (idx & 7) << 2;                           \
            uint4 u;                                                        \
            u.x = f2tf(bSt[i].x); u.y = f2tf(bSt[i].y);                     \
            u.z = f2tf(bSt[i].z); u.w = f2tf(bSt[i].w);                     \
            *(uint4*)&Bs_[r * G_PA + c] = u;                                \
        }                                                                   \
    }

    G_LOAD(0);
    G_STORE(0);
    __syncthreads();

    for (int kk = 0; kk < GK; kk += 32) {
        const int buf = (kk >> 5) & 1;
        const bool more = (kk + 32) < GK;
        if (more) G_LOAD(kk + 32);

        const unsigned* As = smg + buf * G_BUF;
        const unsigned* Bs = As + G_ABUF;

#pragma unroll
        for (int ks = 0; ks < 4; ks++) {
            const int k = ks * 8;
            unsigned af[4][4], bf[8][2];
#pragma unroll
            for (int mt = 0; mt < 4; mt++) {
                int r = wm * 64 + mt * 16 + g;
                af[mt][0] = As[r * G_PA + k + q];
                af[mt][1] = As[(r + 8) * G_PA + k + q];
                af[mt][2] = As[r * G_PA + k + q + 4];
                af[mt][3] = As[(r + 8) * G_PA + k + q + 4];
            }
#pragma unroll
            for (int nt = 0; nt < 8; nt++) {
                int cc = wn * 64 + nt * 8 + g;
                bf[nt][0] = Bs[cc * G_PA + k + q];
                bf[nt][1] = Bs[cc * G_PA + k + q + 4];
            }
#pragma unroll
            for (int mt = 0; mt < 4; mt++)
#pragma unroll
                for (int nt = 0; nt < 8; nt++)
                    mma_tf32(acc[mt][nt], af[mt][0], af[mt][1], af[mt][2], af[mt][3],
                             bf[nt][0], bf[nt][1]);
        }

        if (more) G_STORE(buf ^ 1);
        __syncthreads();
    }

#pragma unroll
    for (int mt = 0; mt < 4; mt++) {
        int m0 = bm * 256 + wm * 64 + mt * 16 + g;
        int m1 = m0 + 8;
#pragma unroll
        for (int nt = 0; nt < 8; nt++) {
            int n0 = bn * 128 + wn * 64 + nt * 8 + 2 * q;
            int n1 = n0 + 1;
            float b0 = bias[n0], b1 = bias[n1];
            float v00 = acc[mt][nt][0] + b0;
            float v01 = acc[mt][nt][1] + b1;
            float v10 = acc[mt][nt][2] + b0;
            float v11 = acc[mt][nt][3] + b1;
            if (HEADED) {
                int bb0 = m0 / SEQ, t0 = m0 % SEQ;
                int bb1 = m1 / SEQ, t1 = m1 % SEQ;
                int h0 = n0 >> 6, d0 = n0 & 63;
                int h1 = n1 >> 6, d1 = n1 & 63;
                C[(((size_t)(bb0 * N_HEADS + h0) * SEQ) + t0) * HEAD_DIM + d0] = v00;
                C[(((size_t)(bb0 * N_HEADS + h1) * SEQ) + t0) * HEAD_DIM + d1] = v01;
                C[(((size_t)(bb1 * N_HEADS + h0) * SEQ) + t1) * HEAD_DIM + d0] = v10;
                C[(((size_t)(bb1 * N_HEADS + h1) * SEQ) + t1) * HEAD_DIM + d1] = v11;
            } else {
                C[(size_t)m0 * GN + n0] = v00;
                C[(size_t)m0 * GN + n1] = v01;
                C[(size_t)m1 * GN + n0] = v10;
                C[(size_t)m1 * GN + n1] = v11;
            }
        }
    }
#undef G_LOAD
#undef G_STORE
}

// ---------------------------------------------------------------------------
// Flash attention v2: CTA = 128 q-rows for one (b,h), 64-key tiles.
// 8 warps; warp w owns rows [w*16, w*16+16) across the FULL key width.
// Softmax is warp-local (quad shuffles only). P roundtrips through a
// per-warp smem region guarded by __syncwarp(). 2 CTA-wide barriers/tile.
// Pitches: Qs/Ks/Ps 68 (conflict-free frags), Vs 72 (conflict-free B frags).
// ---------------------------------------------------------------------------
#define AKP 68
#define AVP 72
#define A_KS 0
#define A_VS (64 * AKP)                      // 4352
#define A_QS (A_VS + 64 * AVP)               // 8960
#define A_PS (A_QS + 128 * AKP)              // 17664
#define ATTN_SMEM ((A_PS + 128 * AKP) * 4)   // 105472 bytes

__global__ void __launch_bounds__(256, 2) attn_tf32_kernel(
    const float* __restrict__ Q, const float* __restrict__ K,
    const float* __restrict__ V, float* __restrict__ Y)
{
    extern __shared__ unsigned sma[];
    unsigned* Ks = sma + A_KS;
    unsigned* Vs = sma + A_VS;
    unsigned* Qs = sma + A_QS;
    unsigned* Ps = sma + A_PS;

    const int tid  = threadIdx.x;
    const int lane = tid & 31;
    const int w    = tid >> 5;
    const int g    = lane >> 2;
    const int q    = lane & 3;
    const int qt   = (int)gridDim.x - 1 - (int)blockIdx.x;  // heavy tiles first
    const int bh   = blockIdx.y;
    const int q0   = qt * 128;

    const int r0  = w * 16 + g;      // local rows owned by this thread
    const int r1  = r0 + 8;
    const int gr0 = q0 + r0;         // global rows
    const int gr1 = q0 + r1;
    const int gw0 = q0 + w * 16;     // warp's first global row

    // ---- Stage Q (fp32 -> tf32) into Qs
    {
        const float* Qp = Q + ((size_t)bh * SEQ + q0) * HEAD_DIM;
#pragma unroll
        for (int i = 0; i < 8; i++) {
            int idx = i * 256 + tid;
            int row = idx >> 4, c4 = (idx & 15) << 2;
            float4 v = *(const float4*)(Qp + row * HEAD_DIM + c4);
            uint4 u;
            u.x = f2tf(v.x); u.y = f2tf(v.y); u.z = f2tf(v.z); u.w = f2tf(v.w);
            *(uint4*)&Qs[row * AKP + c4] = u;
        }
    }

    float o[8][4];
#pragma unroll
    for (int nt = 0; nt < 8; nt++)
#pragma unroll
        for (int i = 0; i < 4; i++) o[nt][i] = 0.0f;
    float m0 = -1e30f, m1 = -1e30f, l0 = 0.0f, l1 = 0.0f;

    const int kt_max = 2 * qt + 2;

    for (int kt = 0; kt < kt_max; kt++) {
        __syncthreads();   // protect Ks/Vs reuse (and Qs staging on kt=0)
        const int k0 = kt * 64;
        {
            const float* Kp = K + ((size_t)bh * SEQ + k0) * HEAD_DIM;
            const float* Vp = V + ((size_t)bh * SEQ + k0) * HEAD_DIM;
#pragma unroll
            for (int i = 0; i < 4; i++) {
                int idx = i * 256 + tid;
                int row = idx >> 4, c4 = (idx & 15) << 2;
                float4 kv = *(const float4*)(Kp + row * HEAD_DIM + c4);
                uint4 uk;
                uk.x = f2tf(kv.x); uk.y = f2tf(kv.y); uk.z = f2tf(kv.z); uk.w = f2tf(kv.w);
                *(uint4*)&Ks[row * AKP + c4] = uk;
                float4 vv = *(const float4*)(Vp + row * HEAD_DIM + c4);
                uint4 uv;
                uv.x = f2tf(vv.x); uv.y = f2tf(vv.y); uv.z = f2tf(vv.z); uv.w = f2tf(vv.w);
                *(uint4*)&Vs[row * AVP + c4] = uv;
            }
        }
        __syncthreads();

        if (k0 <= gw0 + 15) {   // warp has at least one visible row
            // ---- S = Q @ K^T : 16 rows x 64 keys
            float sc[8][4];
#pragma unroll
            for (int nt = 0; nt < 8; nt++)
#pragma unroll
                for (int i = 0; i < 4; i++) sc[nt][i] = 0.0f;

#pragma unroll
            for (int ks = 0; ks < 8; ks++) {
                const int k = ks * 8;
                unsigned a0 = Qs[r0 * AKP + k + q];
                unsigned a1 = Qs[r1 * AKP + k + q];
                unsigned a2 = Qs[r0 * AKP + k + q + 4];
                unsigned a3 = Qs[r1 * AKP + k + q + 4];
#pragma unroll
                for (int nt = 0; nt < 8; nt++) {
                    unsigned b0 = Ks[(nt * 8 + g) * AKP + k + q];
                    unsigned b1 = Ks[(nt * 8 + g) * AKP + k + q + 4];
                    mma_tf32(sc[nt], a0, a1, a2, a3, b0, b1);
                }
            }

            // ---- scale + causal mask
            const bool need_mask = (k0 + 63 > gr0 - g);  // any masked key for this warp
#pragma unroll
            for (int nt = 0; nt < 8; nt++) {
                int ck = k0 + nt * 8 + 2 * q;
                sc[nt][0] *= 0.125f; sc[nt][1] *= 0.125f;
                sc[nt][2] *= 0.125f; sc[nt][3] *= 0.125f;
                if (need_mask) {
                    if (ck     > gr0) sc[nt][0] = -1e30f;
                    if (ck + 1 > gr0) sc[nt][1] = -1e30f;
                    if (ck     > gr1) sc[nt][2] = -1e30f;
                    if (ck + 1 > gr1) sc[nt][3] = -1e30f;
                }
            }

            // ---- warp-local online softmax (rows live in one quad)
            float rm0 = -1e30f, rm1 = -1e30f;
#pragma unroll
            for (int nt = 0; nt < 8; nt++) {
                rm0 = fmaxf(rm0, fmaxf(sc[nt][0], sc[nt][1]));
                rm1 = fmaxf(rm1, fmaxf(sc[nt][2], sc[nt][3]));
            }
            rm0 = fmaxf(rm0, __shfl_xor_sync(0xffffffffu, rm0, 1));
            rm0 = fmaxf(rm0, __shfl_xor_sync(0xffffffffu, rm0, 2));
            rm1 = fmaxf(rm1, __shfl_xor_sync(0xffffffffu, rm1, 1));
            rm1 = fmaxf(rm1, __shfl_xor_sync(0xffffffffu, rm1, 2));

            float nm0 = fmaxf(m0, rm0);
            float nm1 = fmaxf(m1, rm1);
            float cr0 = __expf(m0 - nm0);
            float cr1 = __expf(m1 - nm1);

            float s0 = 0.0f, s1 = 0.0f;
#pragma unroll
            for (int nt = 0; nt < 8; nt++) {
                sc[nt][0] = __expf(sc[nt][0] - nm0);
                sc[nt][1] = __expf(sc[nt][1] - nm0);
                sc[nt][2] = __expf(sc[nt][2] - nm1);
                sc[nt][3] = __expf(sc[nt][3] - nm1);
                s0 += sc[nt][0] + sc[nt][1];
                s1 += sc[nt][2] + sc[nt][3];
            }
            s0 += __shfl_xor_sync(0xffffffffu, s0, 1);
            s0 += __shfl_xor_sync(0xffffffffu, s0, 2);
            s1 += __shfl_xor_sync(0xffffffffu, s1, 1);
            s1 += __shfl_xor_sync(0xffffffffu, s1, 2);

            l0 = l0 * cr0 + s0;
            l1 = l1 * cr1 + s1;
            m0 = nm0; m1 = nm1;

            // rescale O in registers
#pragma unroll
            for (int nt = 0; nt < 8; nt++) {
                o[nt][0] *= cr0; o[nt][1] *= cr0;
                o[nt][2] *= cr1; o[nt][3] *= cr1;
            }

            // ---- P -> per-warp smem (only this warp reads it back)
#pragma unroll
            for (int nt = 0; nt < 8; nt++) {
                int col = nt * 8 + 2 * q;
                uint2 p0; p0.x = f2tf(sc[nt][0]); p0.y = f2tf(sc[nt][1]);
                *(uint2*)&Ps[r0 * AKP + col] = p0;
                uint2 p1; p1.x = f2tf(sc[nt][2]); p1.y = f2tf(sc[nt][3]);
                *(uint2*)&Ps[r1 * AKP + col] = p1;
            }
            __syncwarp();

            // ---- O += P @ V
#pragma unroll
            for (int ks = 0; ks < 8; ks++) {
                const int k = ks * 8;
                unsigned a0 = Ps[r0 * AKP + k + q];
                unsigned a1 = Ps[r1 * AKP + k + q];
                unsigned a2 = Ps[r0 * AKP + k + q + 4];
                unsigned a3 = Ps[r1 * AKP + k + q + 4];
#pragma unroll
                for (int nt = 0; nt < 8; nt++) {
                    unsigned b0 = Vs[(k + q) * AVP + nt * 8 + g];
                    unsigned b1 = Vs[(k + q + 4) * AVP + nt * 8 + g];
                    mma_tf32(o[nt], a0, a1, a2, a3, b0, b1);
                }
            }
        }
    }

    // ---- epilogue: normalize, write Y[b, t, h*64 + d]
    const float inv0 = 1.0f / l0;
    const float inv1 = 1.0f / l1;
    const int b = bh >> 4;
    const int h = bh & 15;
    float* y0 = Y + ((size_t)b * SEQ + gr0) * D_MODEL + h * HEAD_DIM;
    float* y1 = Y + ((size_t)b * SEQ + gr1) * D_MODEL + h * HEAD_DIM;
#pragma unroll
    for (int nt = 0; nt < 8; nt++) {
        int d = nt * 8 + 2 * q;
        float2 v0; v0.x = o[nt][0] * inv0; v0.y = o[nt][1] * inv0;
        *(float2*)&y0[d] = v0;
        float2 v1; v1.x = o[nt][2] * inv1; v1.y = o[nt][3] * inv1;
        *(float2*)&y1[d] = v1;
    }
}

// ---------------------------------------------------------------------------
// Launch
// ---------------------------------------------------------------------------
extern "C" void kernel_launch(void* const* d_in, const int* in_sizes, int n_in,
                              void* d_out, int out_size)
{
    const float* x  = (const float*)d_in[0];
    const float* Wq = (const float*)d_in[1];
    const float* bq = (const float*)d_in[2];
    const float* Wk = (const float*)d_in[3];
    const float* bk = (const float*)d_in[4];
    const float* Wv = (const float*)d_in[5];
    const float* bv = (const float*)d_in[6];
    const float* Wo = (const float*)d_in[7];
    const float* bo = (const float*)d_in[8];
    float* out = (float*)d_out;

    float *Qb, *Kb, *Vb, *Yb;
    cudaGetSymbolAddress((void**)&Qb, g_Q);
    cudaGetSymbolAddress((void**)&Kb, g_K);
    cudaGetSymbolAddress((void**)&Vb, g_V);
    cudaGetSymbolAddress((void**)&Yb, g_Y);

    static bool attr_set = false;
    if (!attr_set) {
        cudaFuncSetAttribute(gemm_tf32_kernel<true>,
                             cudaFuncAttributeMaxDynamicSharedMemorySize, GEMM_SMEM);
        cudaFuncSetAttribute(gemm_tf32_kernel<false>,
                             cudaFuncAttributeMaxDynamicSharedMemorySize, GEMM_SMEM);
        cudaFuncSetAttribute(attn_tf32_kernel,
                             cudaFuncAttributeMaxDynamicSharedMemorySize, ATTN_SMEM);
        attr_set = true;
    }

    // Fused QKV projections
    dim3 qkvgrid(GN / 128, M_TOTAL / 256, 3);   // (8, 32, 3)
    gemm_tf32_kernel<true><<<qkvgrid, 256, GEMM_SMEM>>>(
        x, Wq, bq, Qb, Wk, bk, Kb, Wv, bv, Vb);

    dim3 agrid(SEQ / 128, BATCH * N_HEADS);     // (16, 64)
    attn_tf32_kernel<<<agrid, 256, ATTN_SMEM>>>(Qb, Kb, Vb, Yb);

    dim3 ogrid(GN / 128, M_TOTAL / 256, 1);     // (8, 32)
    gemm_tf32_kernel<false><<<ogrid, 256, GEMM_SMEM>>>(
        Yb, Wo, bo, out, Wo, bo, out, Wo, bo, out);
}